// round 1
// baseline (speedup 1.0000x reference)
#include <cuda_runtime.h>
#include <cuda_fp16.h>
#include <cstdint>
#include <cstddef>

// Problem shape (fixed by the dataset)
#define NB 4
#define HH 256
#define WW 256
#define CC 96
#define NF 4
#define CT 16                 // channels per CTA tile
#define NTHR 64               // NF * CT

// Filter coefficients in FILTER_IDS order (1,3,4,8)
__constant__ float c_a[NF] = {0.1f, 0.3f, 0.4f, 0.8f};

// Intermediate: horizontal IIR result per filter, fp16, layout [f][n][h][w][c]
#define PLANE ((size_t)NB * HH * WW * CC)
__device__ __half g_mid[(size_t)NF * PLANE];
__device__ float  g_wts[NF * CC];

// ---------------------------------------------------------------------------
// K0: per-channel softmax over the 4 filter logits
// ---------------------------------------------------------------------------
__global__ void softmax_k(const float* __restrict__ gl) {
    int c = threadIdx.x;
    if (c >= CC) return;
    float v0 = gl[0 * CC + c], v1 = gl[1 * CC + c];
    float v2 = gl[2 * CC + c], v3 = gl[3 * CC + c];
    float m = fmaxf(fmaxf(v0, v1), fmaxf(v2, v3));
    float e0 = expf(v0 - m), e1 = expf(v1 - m);
    float e2 = expf(v2 - m), e3 = expf(v3 - m);
    float r = 1.0f / (e0 + e1 + e2 + e3);
    g_wts[0 * CC + c] = e0 * r;
    g_wts[1 * CC + c] = e1 * r;
    g_wts[2 * CC + c] = e2 * r;
    g_wts[3 * CC + c] = e3 * r;
}

// ---------------------------------------------------------------------------
// K1: horizontal bidirectional IIR, all 4 filters.
// Exact closed form of the reference (carry-init = x[0]) scans:
//   F~[t] = x[t] + a F~[t-1],  F~ "carry" init = x0/(1-a)
//   g[t]  = x[t] + a g[t+1],   g  carry init  = F~[L-1]
//   y[t]  = cf * (F~[t] + g[t] - x[t]),  cf = (1-a)/(1+a)
// CTA: one (n, h, 16-channel block). 64 threads = (f, c) lanes.
// ---------------------------------------------------------------------------
#define FSTR1 (WW * CT + 16)   // padded f-stride (floats): +16 -> 16-bank shift

__global__ void hscan_k(const float* __restrict__ x) {
    const int cblk = blockIdx.x, h = blockIdx.y, n = blockIdx.z;
    extern __shared__ float sm1[];
    float* xs = sm1;               // [WW*CT]
    float* Fb = sm1 + WW * CT;     // [NF][FSTR1]

    const float* src = x + ((size_t)(n * HH + h) * WW) * CC + cblk * CT;

    // Cooperative load: 256 w * 16 c floats, as float4 (coalesced, full sectors)
    for (int i = threadIdx.x; i < (WW * CT) / 4; i += NTHR) {
        int w = i >> 2, q = (i & 3) * 4;
        float4 v = *(const float4*)(src + (size_t)w * CC + q);
        *(float4*)(xs + w * CT + q) = v;
    }
    __syncthreads();

    const int f = threadIdx.x >> 4;
    const int c = threadIdx.x & (CT - 1);
    const float a  = c_a[f];
    const float cf = (1.0f - a) / (1.0f + a);
    float* F = Fb + f * FSTR1;

    // Forward scan
    float carry = xs[c] / (1.0f - a);
    #pragma unroll 8
    for (int w = 0; w < WW; ++w) {
        carry = fmaf(a, carry, xs[w * CT + c]);
        F[w * CT + c] = carry;
    }

    // Backward scan + combine, write fp16 intermediate
    __half* dst = g_mid + (size_t)f * PLANE
                + ((size_t)(n * HH + h) * WW) * CC + cblk * CT + c;
    float g = carry;   // g-carry init = F~[L-1]
    #pragma unroll 8
    for (int w = WW - 1; w >= 0; --w) {
        float xv = xs[w * CT + c];
        g = fmaf(a, g, xv);
        float y = cf * (F[w * CT + c] + g - xv);
        dst[(size_t)w * CC] = __float2half(y);
    }
}

// ---------------------------------------------------------------------------
// K2: vertical bidirectional IIR on the fp16 intermediate + weighted combine.
// CTA: one (n, w, 16-channel block). 64 threads = (f, c) lanes.
// ---------------------------------------------------------------------------
#define RSTR2 (HH * CT + 16)   // padded f-stride (halves): 8-bank shift per f
#define FSTR2 (HH * CT + 16)   // padded f-stride (floats): 16-bank shift per f

__global__ void vscan_k(float* __restrict__ out) {
    const int cblk = blockIdx.x, w = blockIdx.y, n = blockIdx.z;
    extern __shared__ float sm2[];
    __half* rt = (__half*)sm2;                       // [NF][RSTR2] halves
    float*  Fb = sm2 + (NF * RSTR2) / 2;             // [NF][FSTR2] floats
    float*  wsm = Fb + NF * FSTR2;                   // [NF*CT]

    // Preload weights (exactly NTHR of them)
    {
        int f = threadIdx.x >> 4, c = threadIdx.x & (CT - 1);
        wsm[threadIdx.x] = g_wts[f * CC + cblk * CT + c];
    }

    // Cooperative load of 4f x 256h x 16c halves (32B rows -> full sectors)
    for (int i = threadIdx.x; i < NF * HH * 2; i += NTHR) {
        int f = i >> 9, h = (i >> 1) & (HH - 1), q = (i & 1) * 8;
        const __half* p = g_mid + (size_t)f * PLANE
                        + ((size_t)(n * HH + h) * WW + w) * CC + cblk * CT + q;
        uint4 v = *(const uint4*)p;
        *(uint4*)(rt + f * RSTR2 + h * CT + q) = v;
    }
    __syncthreads();

    const int f = threadIdx.x >> 4;
    const int c = threadIdx.x & (CT - 1);
    const float a  = c_a[f];
    const float cf = (1.0f - a) / (1.0f + a);
    const __half* R = rt + f * RSTR2;
    float* F = Fb + f * FSTR2;

    // Forward scan over h
    float carry = __half2float(R[c]) / (1.0f - a);
    #pragma unroll 8
    for (int h = 0; h < HH; ++h) {
        carry = fmaf(a, carry, __half2float(R[h * CT + c]));
        F[h * CT + c] = carry;
    }

    // Backward scan + combine, overwrite F with per-filter result
    float g = carry;
    #pragma unroll 8
    for (int h = HH - 1; h >= 0; --h) {
        float rv = __half2float(R[h * CT + c]);
        g = fmaf(a, g, rv);
        F[h * CT + c] = cf * (F[h * CT + c] + g - rv);
    }
    __syncthreads();

    // Weighted sum over filters, coalesced fp32 store
    for (int i = threadIdx.x; i < HH * CT; i += NTHR) {
        int h = i >> 4, c2 = i & (CT - 1);
        float o = wsm[0 * CT + c2] * Fb[0 * FSTR2 + i]
                + wsm[1 * CT + c2] * Fb[1 * FSTR2 + i]
                + wsm[2 * CT + c2] * Fb[2 * FSTR2 + i]
                + wsm[3 * CT + c2] * Fb[3 * FSTR2 + i];
        out[((size_t)(n * HH + h) * WW + w) * CC + cblk * CT + c2] = o;
    }
}

// ---------------------------------------------------------------------------
extern "C" void kernel_launch(void* const* d_in, const int* in_sizes, int n_in,
                              void* d_out, int out_size) {
    const float* x  = (const float*)d_in[0];
    const float* gl = (const float*)d_in[1];
    float* out = (float*)d_out;

    const int smem1 = (WW * CT + NF * FSTR1) * (int)sizeof(float);
    const int smem2 = (NF * RSTR2) * (int)sizeof(__half)
                    + (NF * FSTR2 + NF * CT) * (int)sizeof(float);

    cudaFuncSetAttribute(hscan_k, cudaFuncAttributeMaxDynamicSharedMemorySize, smem1);
    cudaFuncSetAttribute(vscan_k, cudaFuncAttributeMaxDynamicSharedMemorySize, smem2);

    softmax_k<<<1, CC>>>(gl);

    dim3 g1(CC / CT, HH, NB);
    hscan_k<<<g1, NTHR, smem1>>>(x);

    dim3 g2(CC / CT, WW, NB);
    vscan_k<<<g2, NTHR, smem2>>>(out);

    (void)in_sizes; (void)n_in; (void)out_size;
}

// round 3
// speedup vs baseline: 2.7917x; 2.7917x over previous
#include <cuda_runtime.h>
#include <cuda_fp16.h>
#include <cstdint>
#include <cstddef>

#define NB 4
#define HH 256
#define WW 256
#define CC 96
#define NF 4
#define CT 8                    // channels per CTA
#define NJ 16                   // chunks per row
#define CL 16                   // chunk length
#define NTHR 512                // NJ * CT * NF

// chunk-padded smem strides (conflict-free: bank = 2j + 8i + c)
#define XSTR 130                // floats per chunk (16*8 + 2)
#define XS_F (NJ * XSTR)        // 2080 floats per plane
#define RSTR 132                // halves per chunk (16*8 + 4)
#define RT_F (NJ * RSTR)        // 2112 halves per plane

__constant__ float c_a[NF] = {0.1f, 0.3f, 0.4f, 0.8f};

#define PLANE ((size_t)NB * HH * WW * CC)
__device__ __half g_mid[(size_t)NF * PLANE];
__device__ float  g_wts[NF * CC];

__device__ __forceinline__ unsigned h2_bits(__half2 h) {
    return *reinterpret_cast<unsigned*>(&h);
}

// exact small-integer power by squaring (e in [0,15])
__device__ __forceinline__ float powi16(float A, int e) {
    float r = 1.0f, p = A;
    if (e & 1) r *= p;  p *= p;
    if (e & 2) r *= p;  p *= p;
    if (e & 4) r *= p;  p *= p;
    if (e & 8) r *= p;
    return r;
}

// ---------------------------------------------------------------------------
__global__ void softmax_k(const float* __restrict__ gl) {
    int c = threadIdx.x;
    if (c >= CC) return;
    float v0 = gl[0 * CC + c], v1 = gl[1 * CC + c];
    float v2 = gl[2 * CC + c], v3 = gl[3 * CC + c];
    float m = fmaxf(fmaxf(v0, v1), fmaxf(v2, v3));
    float e0 = expf(v0 - m), e1 = expf(v1 - m);
    float e2 = expf(v2 - m), e3 = expf(v3 - m);
    float r = 1.0f / (e0 + e1 + e2 + e3);
    g_wts[0 * CC + c] = e0 * r;
    g_wts[1 * CC + c] = e1 * r;
    g_wts[2 * CC + c] = e2 * r;
    g_wts[3 * CC + c] = e3 * r;
}

// ---------------------------------------------------------------------------
// K1: horizontal pass. CTA = (cblk, h, n). 512 threads = (j,c,f).
__global__ void hscan_k(const float* __restrict__ x) {
    const int cblk = blockIdx.x, h = blockIdx.y, n = blockIdx.z;
    extern __shared__ float sm1[];
    float* xs = sm1;               // [NJ][XSTR]
    float* ys = sm1 + XS_F;        // [NF][NJ][XSTR]

    const int tid = threadIdx.x;
    const float* src = x + ((size_t)(n * HH + h) * WW) * CC + cblk * CT;

    // cooperative load: 512 float4s (one per thread), swizzled chunk layout
    {
        int w = tid >> 1, q = (tid & 1) * 4;
        float4 v = *(const float4*)(src + (size_t)w * CC + q);
        float* d = xs + (w >> 4) * XSTR + (w & 15) * CT + q;
        *(float2*)(d)     = make_float2(v.x, v.y);
        *(float2*)(d + 2) = make_float2(v.z, v.w);
    }
    __syncthreads();

    const int j = tid & 15;
    const int c = (tid >> 4) & 7;
    const int f = tid >> 7;
    const float a = c_a[f];
    const float A = powi16(a, 8); const float A16 = A * A;   // a^16
    const float cf = (1.0f - a) / (1.0f + a);
    const unsigned FM = 0xffffffffu;

    float xv[CL];
    {
        const float* xp = xs + j * XSTR + c;
        #pragma unroll
        for (int i = 0; i < CL; ++i) xv[i] = xp[i * CT];
    }

    // local forward scan (zero carry) -> chunk tail L
    float t = 0.0f;
    #pragma unroll
    for (int i = 0; i < CL; ++i) t = fmaf(a, t, xv[i]);
    float L = t;

    // carry scan over chunks: s_j = sum_{m<=j} A16^{j-m} L_m
    float s = L, Ad = A16;
    #pragma unroll
    for (int d = 1; d < 16; d <<= 1) {
        float u = __shfl_up_sync(FM, s, d, 16);
        if (j >= d) s = fmaf(Ad, u, s);
        Ad *= Ad;
    }
    float P = __shfl_up_sync(FM, s, 1, 16);
    float x0 = __shfl_sync(FM, xv[0], 0, 16);
    float c0 = x0 / (1.0f - a);
    float cin = (j == 0) ? c0 : fmaf(powi16(A16, j), c0, P);

    // recompute forward with true carry
    float Fv[CL];
    t = cin;
    #pragma unroll
    for (int i = 0; i < CL; ++i) { t = fmaf(a, t, xv[i]); Fv[i] = t; }
    float F255 = __shfl_sync(FM, t, 15, 16);

    // local backward (zero carry) -> chunk head LB
    t = 0.0f;
    #pragma unroll
    for (int i = CL - 1; i >= 0; --i) t = fmaf(a, t, xv[i]);
    float LB = t;

    // reverse carry scan: s_j = sum_{m>=j} A16^{m-j} LB_m
    s = LB; Ad = A16;
    #pragma unroll
    for (int d = 1; d < 16; d <<= 1) {
        float u = __shfl_down_sync(FM, s, d, 16);
        if (j + d < 16) s = fmaf(Ad, u, s);
        Ad *= Ad;
    }
    float Pb = __shfl_down_sync(FM, s, 1, 16);
    if (j == 15) Pb = 0.0f;
    float gin = fmaf(powi16(A16, 15 - j), F255, Pb);

    // recompute backward with true carry, combine, stage y (fp32, swizzled)
    {
        float* yp = ys + f * XS_F + j * XSTR + c;
        t = gin;
        #pragma unroll
        for (int i = CL - 1; i >= 0; --i) {
            t = fmaf(a, t, xv[i]);
            yp[i * CT] = cf * (Fv[i] + t - xv[i]);
        }
    }
    __syncthreads();

    // pack to fp16 and store coalesced: 1024 (f,w) units, 16B each
    __half* base = g_mid + ((size_t)(n * HH + h) * WW) * CC + cblk * CT;
    #pragma unroll
    for (int u = tid; u < NF * WW; u += NTHR) {
        int ff = u >> 8, w = u & 255;
        const float* yq = ys + ff * XS_F + (w >> 4) * XSTR + (w & 15) * CT;
        float2 p0 = *(const float2*)(yq);
        float2 p1 = *(const float2*)(yq + 2);
        float2 p2 = *(const float2*)(yq + 4);
        float2 p3 = *(const float2*)(yq + 6);
        __half2 h0 = __floats2half2_rn(p0.x, p0.y);
        __half2 h1 = __floats2half2_rn(p1.x, p1.y);
        __half2 h2 = __floats2half2_rn(p2.x, p2.y);
        __half2 h3 = __floats2half2_rn(p3.x, p3.y);
        uint4 o;
        o.x = h2_bits(h0); o.y = h2_bits(h1);
        o.z = h2_bits(h2); o.w = h2_bits(h3);
        *(uint4*)(base + (size_t)ff * PLANE + (size_t)w * CC) = o;
    }
}

// K2: vertical pass + weighted combine. CTA = (cblk, w, n).
__global__ void vscan_k(float* __restrict__ out) {
    const int cblk = blockIdx.x, w = blockIdx.y, n = blockIdx.z;
    extern __shared__ float sm2[];
    __half* rt  = (__half*)sm2;                   // [NF][NJ][RSTR] halves
    float*  ysf = sm2 + (NF * RT_F) / 2;          // [NF][NJ][XSTR] floats
    float*  wsm = ysf + NF * XS_F;                // [NF*CT]

    const int tid = threadIdx.x;
    if (tid < NF * CT)
        wsm[tid] = g_wts[(tid >> 3) * CC + cblk * CT + (tid & 7)];

    // cooperative load: 1024 (f,h) 16B segments
    #pragma unroll
    for (int u = tid; u < NF * HH; u += NTHR) {
        int ff = u >> 8, h = u & 255;
        const __half* p = g_mid + (size_t)ff * PLANE
                        + ((size_t)(n * HH + h) * WW + w) * CC + cblk * CT;
        uint4 v = *(const uint4*)p;
        __half* d = rt + ff * RT_F + (h >> 4) * RSTR + (h & 15) * CT;
        *(uint2*)(d)     = make_uint2(v.x, v.y);
        *(uint2*)(d + 4) = make_uint2(v.z, v.w);
    }
    __syncthreads();

    const int j = tid & 15;
    const int c = (tid >> 4) & 7;
    const int f = tid >> 7;
    const float a = c_a[f];
    const float A = powi16(a, 8); const float A16 = A * A;
    const float cf = (1.0f - a) / (1.0f + a);
    const unsigned FM = 0xffffffffu;

    float xv[CL];
    {
        const __half* rp = rt + f * RT_F + j * RSTR + c;
        #pragma unroll
        for (int i = 0; i < CL; ++i) xv[i] = __half2float(rp[i * CT]);
    }

    float t = 0.0f;
    #pragma unroll
    for (int i = 0; i < CL; ++i) t = fmaf(a, t, xv[i]);
    float L = t;

    float s = L, Ad = A16;
    #pragma unroll
    for (int d = 1; d < 16; d <<= 1) {
        float u = __shfl_up_sync(FM, s, d, 16);
        if (j >= d) s = fmaf(Ad, u, s);
        Ad *= Ad;
    }
    float P = __shfl_up_sync(FM, s, 1, 16);
    float x0 = __shfl_sync(FM, xv[0], 0, 16);
    float c0 = x0 / (1.0f - a);
    float cin = (j == 0) ? c0 : fmaf(powi16(A16, j), c0, P);

    float Fv[CL];
    t = cin;
    #pragma unroll
    for (int i = 0; i < CL; ++i) { t = fmaf(a, t, xv[i]); Fv[i] = t; }
    float Flast = __shfl_sync(FM, t, 15, 16);

    t = 0.0f;
    #pragma unroll
    for (int i = CL - 1; i >= 0; --i) t = fmaf(a, t, xv[i]);
    float LB = t;

    s = LB; Ad = A16;
    #pragma unroll
    for (int d = 1; d < 16; d <<= 1) {
        float u = __shfl_down_sync(FM, s, d, 16);
        if (j + d < 16) s = fmaf(Ad, u, s);
        Ad *= Ad;
    }
    float Pb = __shfl_down_sync(FM, s, 1, 16);
    if (j == 15) Pb = 0.0f;
    float gin = fmaf(powi16(A16, 15 - j), Flast, Pb);

    {
        const float wt = wsm[f * CT + c] * cf;
        float* yp = ysf + f * XS_F + j * XSTR + c;
        t = gin;
        #pragma unroll
        for (int i = CL - 1; i >= 0; --i) {
            t = fmaf(a, t, xv[i]);
            yp[i * CT] = wt * (Fv[i] + t - xv[i]);
        }
    }
    __syncthreads();

    // combine 4 filters + coalesced fp32 store: 512 (h, half-row) units
    {
        int hh = tid >> 1, q = (tid & 1) * 4;
        int off = (hh >> 4) * XSTR + (hh & 15) * CT + q;
        float2 a0 = *(const float2*)(ysf + 0 * XS_F + off);
        float2 b0 = *(const float2*)(ysf + 0 * XS_F + off + 2);
        float2 a1 = *(const float2*)(ysf + 1 * XS_F + off);
        float2 b1 = *(const float2*)(ysf + 1 * XS_F + off + 2);
        float2 a2 = *(const float2*)(ysf + 2 * XS_F + off);
        float2 b2 = *(const float2*)(ysf + 2 * XS_F + off + 2);
        float2 a3 = *(const float2*)(ysf + 3 * XS_F + off);
        float2 b3 = *(const float2*)(ysf + 3 * XS_F + off + 2);
        float4 o;
        o.x = a0.x + a1.x + a2.x + a3.x;
        o.y = a0.y + a1.y + a2.y + a3.y;
        o.z = b0.x + b1.x + b2.x + b3.x;
        o.w = b0.y + b1.y + b2.y + b3.y;
        *(float4*)(out + ((size_t)(n * HH + hh) * WW + w) * CC + cblk * CT + q) = o;
    }
}

// ---------------------------------------------------------------------------
extern "C" void kernel_launch(void* const* d_in, const int* in_sizes, int n_in,
                              void* d_out, int out_size) {
    const float* x  = (const float*)d_in[0];
    const float* gl = (const float*)d_in[1];
    float* out = (float*)d_out;

    const int smem1 = (XS_F + NF * XS_F) * (int)sizeof(float);
    const int smem2 = NF * RT_F * (int)sizeof(__half)
                    + (NF * XS_F + NF * CT) * (int)sizeof(float);

    cudaFuncSetAttribute(hscan_k, cudaFuncAttributeMaxDynamicSharedMemorySize, smem1);
    cudaFuncSetAttribute(vscan_k, cudaFuncAttributeMaxDynamicSharedMemorySize, smem2);

    softmax_k<<<1, CC>>>(gl);

    dim3 g1(CC / CT, HH, NB);
    hscan_k<<<g1, NTHR, smem1>>>(x);

    dim3 g2(CC / CT, WW, NB);
    vscan_k<<<g2, NTHR, smem2>>>(out);

    (void)in_sizes; (void)n_in; (void)out_size;
}

// round 6
// speedup vs baseline: 2.8595x; 1.0243x over previous
#include <cuda_runtime.h>
#include <cuda_fp16.h>
#include <cstdint>
#include <cstddef>

#define NB 4
#define HH 256
#define WW 256
#define CC 96
#define NF 4
#define CT 8                    // channels per CTA
#define NJ 16                   // chunks per row
#define CL 16                   // chunk length
#define NTHR 512                // NJ * CT * NF

// chunk-padded smem strides
#define XSTR 130                // floats per chunk (16*8 + 2)
#define XS_F (NJ * XSTR)        // 2080 floats per plane
#define RSTR 132                // halves per chunk (16*8 + 4)
#define RT_F (NJ * RSTR)        // 2112 halves per plane

__constant__ float c_a[NF]   = {0.1f, 0.3f, 0.4f, 0.8f};
__constant__ float c_cf[NF]  = {0.81818181818f, 0.53846153846f, 0.42857142857f, 0.11111111111f}; // (1-a)/(1+a)
__constant__ float c_i1m[NF] = {1.11111111111f, 1.42857142857f, 1.66666666667f, 5.0f};           // 1/(1-a)

#define PLANE ((size_t)NB * HH * WW * CC)
__device__ __half g_mid[(size_t)NF * PLANE];
__device__ float  g_wts[NF * CC];

__device__ __forceinline__ unsigned h2_bits(__half2 h) {
    return *reinterpret_cast<unsigned*>(&h);
}

// exact small-integer power by squaring (e in [0,15])
__device__ __forceinline__ float powi16(float A, int e) {
    float r = 1.0f, p = A;
    if (e & 1) r *= p;  p *= p;
    if (e & 2) r *= p;  p *= p;
    if (e & 4) r *= p;  p *= p;
    if (e & 8) r *= p;
    return r;
}

// ---------------------------------------------------------------------------
__global__ void softmax_k(const float* __restrict__ gl) {
    int c = threadIdx.x;
    if (c >= CC) return;
    float v0 = gl[0 * CC + c], v1 = gl[1 * CC + c];
    float v2 = gl[2 * CC + c], v3 = gl[3 * CC + c];
    float m = fmaxf(fmaxf(v0, v1), fmaxf(v2, v3));
    float e0 = expf(v0 - m), e1 = expf(v1 - m);
    float e2 = expf(v2 - m), e3 = expf(v3 - m);
    float r = 1.0f / (e0 + e1 + e2 + e3);
    g_wts[0 * CC + c] = e0 * r;
    g_wts[1 * CC + c] = e1 * r;
    g_wts[2 * CC + c] = e2 * r;
    g_wts[3 * CC + c] = e3 * r;
}

// ---------------------------------------------------------------------------
// Bidirectional chunked scan core. Inputs xv[CL] (left intact); produces
// Yv[i] = F[i] + G[i] - x[i].  j = chunk index (0..15) in low lane bits.
// ---------------------------------------------------------------------------
__device__ __forceinline__ void scan_core(
    const float* __restrict__ xv, float* __restrict__ Yv,
    int j, float a, float A16, float i1m)
{
    const unsigned FM = 0xffffffffu;

    // independent local forward & backward scans (ILP-2)
    float L = 0.0f, LB = 0.0f;
    #pragma unroll
    for (int i = 0; i < CL; ++i) {
        L  = fmaf(a, L,  xv[i]);
        LB = fmaf(a, LB, xv[CL - 1 - i]);
    }

    // interleaved up/down shfl carry scans (independent chains)
    float s1 = L, s2 = LB, Ad = A16;
    #pragma unroll
    for (int d = 1; d < 16; d <<= 1) {
        float u1 = __shfl_up_sync(FM, s1, d, 16);
        float u2 = __shfl_down_sync(FM, s2, d, 16);
        if (j >= d)     s1 = fmaf(Ad, u1, s1);
        if (j + d < 16) s2 = fmaf(Ad, u2, s2);
        Ad *= Ad;
    }
    float P  = __shfl_up_sync(FM, s1, 1, 16);
    float Pb = __shfl_down_sync(FM, s2, 1, 16);
    if (j == 15) Pb = 0.0f;

    float x0 = __shfl_sync(FM, xv[0], 0, 16);
    float c0 = x0 * i1m;
    float cin = (j == 0) ? c0 : fmaf(powi16(A16, j), c0, P);

    // forward tail of this chunk without recompute; F255 = tail of chunk 15
    float Ftail = fmaf(A16, cin, L);
    float F255  = __shfl_sync(FM, Ftail, 15, 16);
    float gin   = fmaf(powi16(A16, 15 - j), F255, Pb);

    // fused recompute, both directions, accumulating into Yv.
    // Position p is touched at iterations p (forward) and CL-1-p (backward);
    // with compile-time k the first touch assigns, the second adds.
    float tf = cin, tb = gin;
    #pragma unroll
    for (int k = 0; k < CL; ++k) {
        const int ib = CL - 1 - k;
        tf = fmaf(a, tf, xv[k]);
        tb = fmaf(a, tb, xv[ib]);
        if (k < CL / 2) {
            Yv[k]  = tf;                // first touch of pos k
            Yv[ib] = tb - xv[ib];       // first touch of pos ib
        } else {
            Yv[k]  += tf;               // backward part already there
            Yv[ib] += tb - xv[ib];      // forward part already there
        }
    }
}

// K1: horizontal pass. CTA = (cblk, h, n). 512 threads = (j,c,f).
__global__ void __launch_bounds__(NTHR, 2) hscan_k(const float* __restrict__ x) {
    const int cblk = blockIdx.x, h = blockIdx.y, n = blockIdx.z;
    extern __shared__ float sm1[];
    float* xs = sm1;               // [NJ][XSTR]
    float* ys = sm1 + XS_F;        // [NF][NJ][XSTR]

    const int tid = threadIdx.x;
    const float* src = x + ((size_t)(n * HH + h) * WW) * CC + cblk * CT;

    {
        int w = tid >> 1, q = (tid & 1) * 4;
        float4 v = *(const float4*)(src + (size_t)w * CC + q);
        float* d = xs + (w >> 4) * XSTR + (w & 15) * CT + q;
        *(float2*)(d)     = make_float2(v.x, v.y);
        *(float2*)(d + 2) = make_float2(v.z, v.w);
    }
    __syncthreads();

    const int j = tid & 15;
    const int c = (tid >> 4) & 7;
    const int f = tid >> 7;
    const float a = c_a[f];
    const float A8 = powi16(a, 8);
    const float A16 = A8 * A8;
    const float cf = c_cf[f];

    float xv[CL], Yv[CL];
    {
        const float* xp = xs + j * XSTR + c;
        #pragma unroll
        for (int i = 0; i < CL; ++i) xv[i] = xp[i * CT];
    }

    scan_core(xv, Yv, j, a, A16, c_i1m[f]);

    {
        float* yp = ys + f * XS_F + j * XSTR + c;
        #pragma unroll
        for (int i = 0; i < CL; ++i)
            yp[i * CT] = cf * Yv[i];
    }
    __syncthreads();

    // pack to fp16 and store coalesced: 1024 (f,w) units, 16B each
    __half* base = g_mid + ((size_t)(n * HH + h) * WW) * CC + cblk * CT;
    #pragma unroll
    for (int u = tid; u < NF * WW; u += NTHR) {
        int ff = u >> 8, w = u & 255;
        const float* yq = ys + ff * XS_F + (w >> 4) * XSTR + (w & 15) * CT;
        float2 p0 = *(const float2*)(yq);
        float2 p1 = *(const float2*)(yq + 2);
        float2 p2 = *(const float2*)(yq + 4);
        float2 p3 = *(const float2*)(yq + 6);
        __half2 h0 = __floats2half2_rn(p0.x, p0.y);
        __half2 h1 = __floats2half2_rn(p1.x, p1.y);
        __half2 h2 = __floats2half2_rn(p2.x, p2.y);
        __half2 h3 = __floats2half2_rn(p3.x, p3.y);
        uint4 o;
        o.x = h2_bits(h0); o.y = h2_bits(h1);
        o.z = h2_bits(h2); o.w = h2_bits(h3);
        *(uint4*)(base + (size_t)ff * PLANE + (size_t)w * CC) = o;
    }
}

// K2: vertical pass + weighted combine. CTA = (cblk, w, n).
__global__ void __launch_bounds__(NTHR, 2) vscan_k(float* __restrict__ out) {
    const int cblk = blockIdx.x, w = blockIdx.y, n = blockIdx.z;
    extern __shared__ float sm2[];
    __half* rt  = (__half*)sm2;                   // [NF][NJ][RSTR] halves
    float*  ysf = sm2 + (NF * RT_F) / 2;          // [NF][NJ][XSTR] floats
    float*  wsm = ysf + NF * XS_F;                // [NF*CT]

    const int tid = threadIdx.x;
    if (tid < NF * CT)
        wsm[tid] = g_wts[(tid >> 3) * CC + cblk * CT + (tid & 7)];

    #pragma unroll
    for (int u = tid; u < NF * HH; u += NTHR) {
        int ff = u >> 8, h = u & 255;
        const __half* p = g_mid + (size_t)ff * PLANE
                        + ((size_t)(n * HH + h) * WW + w) * CC + cblk * CT;
        uint4 v = *(const uint4*)p;
        __half* d = rt + ff * RT_F + (h >> 4) * RSTR + (h & 15) * CT;
        *(uint2*)(d)     = make_uint2(v.x, v.y);
        *(uint2*)(d + 4) = make_uint2(v.z, v.w);
    }
    __syncthreads();

    const int j = tid & 15;
    const int c = (tid >> 4) & 7;
    const int f = tid >> 7;
    const float a = c_a[f];
    const float A8 = powi16(a, 8);
    const float A16 = A8 * A8;
    const float cf = c_cf[f];

    float xv[CL], Yv[CL];
    {
        const __half* rp = rt + f * RT_F + j * RSTR + c;
        #pragma unroll
        for (int i = 0; i < CL; ++i) xv[i] = __half2float(rp[i * CT]);
    }

    scan_core(xv, Yv, j, a, A16, c_i1m[f]);

    {
        const float wt = wsm[f * CT + c] * cf;
        float* yp = ysf + f * XS_F + j * XSTR + c;
        #pragma unroll
        for (int i = 0; i < CL; ++i)
            yp[i * CT] = wt * Yv[i];
    }
    __syncthreads();

    // combine 4 filters + coalesced fp32 store: 512 (h, half-row) units
    {
        int hh = tid >> 1, q = (tid & 1) * 4;
        int off = (hh >> 4) * XSTR + (hh & 15) * CT + q;
        float2 a0 = *(const float2*)(ysf + 0 * XS_F + off);
        float2 b0 = *(const float2*)(ysf + 0 * XS_F + off + 2);
        float2 a1 = *(const float2*)(ysf + 1 * XS_F + off);
        float2 b1 = *(const float2*)(ysf + 1 * XS_F + off + 2);
        float2 a2 = *(const float2*)(ysf + 2 * XS_F + off);
        float2 b2 = *(const float2*)(ysf + 2 * XS_F + off + 2);
        float2 a3 = *(const float2*)(ysf + 3 * XS_F + off);
        float2 b3 = *(const float2*)(ysf + 3 * XS_F + off + 2);
        float4 o;
        o.x = a0.x + a1.x + a2.x + a3.x;
        o.y = a0.y + a1.y + a2.y + a3.y;
        o.z = b0.x + b1.x + b2.x + b3.x;
        o.w = b0.y + b1.y + b2.y + b3.y;
        *(float4*)(out + ((size_t)(n * HH + hh) * WW + w) * CC + cblk * CT + q) = o;
    }
}

// ---------------------------------------------------------------------------
extern "C" void kernel_launch(void* const* d_in, const int* in_sizes, int n_in,
                              void* d_out, int out_size) {
    const float* x  = (const float*)d_in[0];
    const float* gl = (const float*)d_in[1];
    float* out = (float*)d_out;

    const int smem1 = (XS_F + NF * XS_F) * (int)sizeof(float);
    const int smem2 = NF * RT_F * (int)sizeof(__half)
                    + (NF * XS_F + NF * CT) * (int)sizeof(float);

    cudaFuncSetAttribute(hscan_k, cudaFuncAttributeMaxDynamicSharedMemorySize, smem1);
    cudaFuncSetAttribute(vscan_k, cudaFuncAttributeMaxDynamicSharedMemorySize, smem2);

    softmax_k<<<1, CC>>>(gl);

    dim3 g1(CC / CT, HH, NB);
    hscan_k<<<g1, NTHR, smem1>>>(x);

    dim3 g2(CC / CT, WW, NB);
    vscan_k<<<g2, NTHR, smem2>>>(out);

    (void)in_sizes; (void)n_in; (void)out_size;
}

// round 9
// speedup vs baseline: 2.9276x; 1.0238x over previous
#include <cuda_runtime.h>
#include <cuda_fp16.h>
#include <cstdint>
#include <cstddef>

#define NB 4
#define HH 256
#define WW 256
#define CC 96
#define NF 4
#define CT 8                    // channels per CTA
#define NJ 16                   // chunks per row
#define CL 16                   // chunk length
#define NTHR 512                // NJ * CT * NF

#define XSTR 130                // floats per chunk (16*8 + 2)
#define XS_F (NJ * XSTR)        // 2080 floats (input tile)
#define YPS  (NJ * XSTR + 1)    // 2081: y-plane stride, == 1 mod 32 (odd!)
#define RSTR 132                // halves per chunk
#define RT_F (NJ * RSTR)        // 2112 halves per plane

__constant__ float c_a[NF]   = {0.1f, 0.3f, 0.4f, 0.8f};
__constant__ float c_cf[NF]  = {0.81818181818f, 0.53846153846f, 0.42857142857f, 0.11111111111f}; // (1-a)/(1+a)
__constant__ float c_i1m[NF] = {1.11111111111f, 1.42857142857f, 1.66666666667f, 5.0f};           // 1/(1-a)

#define PLANE ((size_t)NB * HH * WW * CC)
__device__ __half g_mid[(size_t)NF * PLANE];

__device__ __forceinline__ unsigned h2_bits(__half2 h) {
    return *reinterpret_cast<unsigned*>(&h);
}

__device__ __forceinline__ float powi16(float A, int e) {
    float r = 1.0f, p = A;
    if (e & 1) r *= p;  p *= p;
    if (e & 2) r *= p;  p *= p;
    if (e & 4) r *= p;  p *= p;
    if (e & 8) r *= p;
    return r;
}

// ---------------------------------------------------------------------------
// Bidirectional chunked scan core: Yv[i] = F[i] + G[i] - x[i].
// j = chunk index (0..15) in low lane bits.
// ---------------------------------------------------------------------------
__device__ __forceinline__ void scan_core(
    const float* __restrict__ xv, float* __restrict__ Yv,
    int j, float a, float A16, float i1m)
{
    const unsigned FM = 0xffffffffu;

    float L = 0.0f, LB = 0.0f;
    #pragma unroll
    for (int i = 0; i < CL; ++i) {
        L  = fmaf(a, L,  xv[i]);
        LB = fmaf(a, LB, xv[CL - 1 - i]);
    }

    float s1 = L, s2 = LB, Ad = A16;
    #pragma unroll
    for (int d = 1; d < 16; d <<= 1) {
        float u1 = __shfl_up_sync(FM, s1, d, 16);
        float u2 = __shfl_down_sync(FM, s2, d, 16);
        if (j >= d)     s1 = fmaf(Ad, u1, s1);
        if (j + d < 16) s2 = fmaf(Ad, u2, s2);
        Ad *= Ad;
    }
    float P  = __shfl_up_sync(FM, s1, 1, 16);
    float Pb = __shfl_down_sync(FM, s2, 1, 16);
    if (j == 15) Pb = 0.0f;

    float x0 = __shfl_sync(FM, xv[0], 0, 16);
    float c0 = x0 * i1m;
    float cin = (j == 0) ? c0 : fmaf(powi16(A16, j), c0, P);

    float Ftail = fmaf(A16, cin, L);
    float F255  = __shfl_sync(FM, Ftail, 15, 16);
    float gin   = fmaf(powi16(A16, 15 - j), F255, Pb);

    float tf = cin, tb = gin;
    #pragma unroll
    for (int k = 0; k < CL; ++k) {
        const int ib = CL - 1 - k;
        tf = fmaf(a, tf, xv[k]);
        tb = fmaf(a, tb, xv[ib]);
        if (k < CL / 2) {
            Yv[k]  = tf;
            Yv[ib] = tb - xv[ib];
        } else {
            Yv[k]  += tf;
            Yv[ib] += tb - xv[ib];
        }
    }
}

// ---------------------------------------------------------------------------
// K1: horizontal pass. CTA = (cblk, h, n). 512 threads = (j,c,f).
__global__ void __launch_bounds__(NTHR, 2) hscan_k(const float* __restrict__ x) {
    const int cblk = blockIdx.x, h = blockIdx.y, n = blockIdx.z;
    extern __shared__ float sm1[];
    float* xs = sm1;               // [NJ][XSTR]
    float* ys = sm1 + XS_F;        // [NF] planes of stride YPS (odd)

    const int tid = threadIdx.x;
    const float* src = x + ((size_t)(n * HH + h) * WW) * CC + cblk * CT;

    // load: lanes at 16B stride in smem, even offsets -> aligned + conflict-free
    {
        int w = tid >> 1, q = (tid & 1) * 4;
        float4 v = *(const float4*)(src + (size_t)w * CC + q);
        float* d = xs + (w >> 4) * XSTR + (w & 15) * CT + q;
        *(float2*)(d)     = make_float2(v.x, v.y);
        *(float2*)(d + 2) = make_float2(v.z, v.w);
    }
    __syncthreads();

    const int j = tid & 15;
    const int c = (tid >> 4) & 7;
    const int f = tid >> 7;
    const float a = c_a[f];
    const float A8 = powi16(a, 8);
    const float A16 = A8 * A8;
    const float cf = c_cf[f];

    float xv[CL], Yv[CL];
    {
        const float* xp = xs + j * XSTR + c;
        #pragma unroll
        for (int i = 0; i < CL; ++i) xv[i] = xp[i * CT];
    }

    scan_core(xv, Yv, j, a, A16, c_i1m[f]);

    {
        float* yp = ys + f * YPS + j * XSTR + c;    // scalar stores, bank = 2j+c+f
        #pragma unroll
        for (int i = 0; i < CL; ++i)
            yp[i * CT] = cf * Yv[i];
    }
    __syncthreads();

    // pack loop: lanes = (j, ff); SCALAR reads (odd plane stride -> 4B align only)
    // bank per instr = 2*pj + pf + const -> all 32 distinct, conflict-free.
    {
        const int pj = tid & 15;          // chunk
        const int pf = (tid >> 4) & 3;    // filter
        const int ps = tid >> 6;          // 0..7
        __half* pb = g_mid + (size_t)pf * PLANE
                   + ((size_t)(n * HH + h) * WW) * CC + cblk * CT;
        #pragma unroll
        for (int t = 0; t < 2; ++t) {
            int i = ps + t * 8;
            const float* yq = ys + pf * YPS + pj * XSTR + i * CT;
            float v0 = yq[0], v1 = yq[1], v2 = yq[2], v3 = yq[3];
            float v4 = yq[4], v5 = yq[5], v6 = yq[6], v7 = yq[7];
            __half2 h0 = __floats2half2_rn(v0, v1);
            __half2 h1 = __floats2half2_rn(v2, v3);
            __half2 h2 = __floats2half2_rn(v4, v5);
            __half2 h3 = __floats2half2_rn(v6, v7);
            uint4 o;
            o.x = h2_bits(h0); o.y = h2_bits(h1);
            o.z = h2_bits(h2); o.w = h2_bits(h3);
            int w = pj * 16 + i;
            *(uint4*)(pb + (size_t)w * CC) = o;
        }
    }
}

// ---------------------------------------------------------------------------
// K2: vertical pass + inline softmax + weighted combine. CTA = (cblk, w, n).
__global__ void __launch_bounds__(NTHR, 2) vscan_k(float* __restrict__ out,
                                                   const float* __restrict__ gl) {
    const int cblk = blockIdx.x, w = blockIdx.y, n = blockIdx.z;
    extern __shared__ float sm2[];
    __half* rt  = (__half*)sm2;                   // [NF][NJ][RSTR] halves
    float*  ysf = sm2 + (NF * RT_F) / 2;          // [NF] planes of stride YPS
    float*  wsm = ysf + NF * YPS;                 // [NF*CT]

    const int tid = threadIdx.x;

    // inline per-channel softmax (8 threads)
    if (tid < CT) {
        int c = cblk * CT + tid;
        float v0 = gl[0 * CC + c], v1 = gl[1 * CC + c];
        float v2 = gl[2 * CC + c], v3 = gl[3 * CC + c];
        float m = fmaxf(fmaxf(v0, v1), fmaxf(v2, v3));
        float e0 = expf(v0 - m), e1 = expf(v1 - m);
        float e2 = expf(v2 - m), e3 = expf(v3 - m);
        float r = 1.0f / (e0 + e1 + e2 + e3);
        wsm[0 * CT + tid] = e0 * r;
        wsm[1 * CT + tid] = e1 * r;
        wsm[2 * CT + tid] = e2 * r;
        wsm[3 * CT + tid] = e3 * r;
    }

    // load stage: lanes chunk-major -> conflict-free smem writes (even offsets)
    {
        const int lj = tid & 15;          // chunk
        const int li = (tid >> 4) & 7;    // i base
        const int lf = tid >> 7;          // filter
        const __half* pbase = g_mid + (size_t)lf * PLANE
                            + ((size_t)n * HH * WW + w) * CC + cblk * CT;
        __half* dbase = rt + lf * RT_F + lj * RSTR;
        #pragma unroll
        for (int t = 0; t < 2; ++t) {
            int i = li + t * 8;
            int h = lj * 16 + i;
            uint4 v = *(const uint4*)(pbase + (size_t)h * WW * CC);
            __half* d = dbase + i * CT;
            *(uint2*)(d)     = make_uint2(v.x, v.y);
            *(uint2*)(d + 4) = make_uint2(v.z, v.w);
        }
    }
    __syncthreads();

    const int j = tid & 15;
    const int c = (tid >> 4) & 7;
    const int f = tid >> 7;
    const float a = c_a[f];
    const float A8 = powi16(a, 8);
    const float A16 = A8 * A8;
    const float cf = c_cf[f];

    float xv[CL], Yv[CL];
    {
        const __half* rp = rt + f * RT_F + j * RSTR + c;
        #pragma unroll
        for (int i = 0; i < CL; ++i) xv[i] = __half2float(rp[i * CT]);
    }

    scan_core(xv, Yv, j, a, A16, c_i1m[f]);

    {
        const float wt = wsm[f * CT + c] * cf;
        float* yp = ysf + f * YPS + j * XSTR + c;
        #pragma unroll
        for (int i = 0; i < CL; ++i)
            yp[i * CT] = wt * Yv[i];
    }
    __syncthreads();

    // combine: lanes = (j2, f2); SCALAR reads (odd plane stride); thread sums
    // planes {f2, f2+2}; shfl_xor(16) merges; 16B aligned global store.
    {
        const int j2 = tid & 15;
        const int f2 = (tid >> 4) & 1;
        const int sl = tid >> 5;          // i = 0..15
        const unsigned FM = 0xffffffffu;
        int off = j2 * XSTR + sl * CT;
        const float* b0 = ysf + f2 * YPS + off;
        const float* b2 = ysf + (f2 + 2) * YPS + off;
        float s[8];
        #pragma unroll
        for (int q = 0; q < 8; ++q)
            s[q] = b0[q] + b2[q];
        #pragma unroll
        for (int q = 0; q < 8; ++q)
            s[q] += __shfl_xor_sync(FM, s[q], 16);

        int h = j2 * 16 + sl;
        float4 o = make_float4(s[f2 * 4], s[f2 * 4 + 1], s[f2 * 4 + 2], s[f2 * 4 + 3]);
        *(float4*)(out + ((size_t)(n * HH + h) * WW + w) * CC + cblk * CT + f2 * 4) = o;
    }
}

// ---------------------------------------------------------------------------
extern "C" void kernel_launch(void* const* d_in, const int* in_sizes, int n_in,
                              void* d_out, int out_size) {
    const float* x  = (const float*)d_in[0];
    const float* gl = (const float*)d_in[1];
    float* out = (float*)d_out;

    const int smem1 = (XS_F + NF * YPS) * (int)sizeof(float);
    const int smem2 = NF * RT_F * (int)sizeof(__half)
                    + (NF * YPS + NF * CT) * (int)sizeof(float);

    cudaFuncSetAttribute(hscan_k, cudaFuncAttributeMaxDynamicSharedMemorySize, smem1);
    cudaFuncSetAttribute(vscan_k, cudaFuncAttributeMaxDynamicSharedMemorySize, smem2);

    dim3 g1(CC / CT, HH, NB);
    hscan_k<<<g1, NTHR, smem1>>>(x);

    dim3 g2(CC / CT, WW, NB);
    vscan_k<<<g2, NTHR, smem2>>>(out, gl);

    (void)in_sizes; (void)n_in; (void)out_size;
}

// round 10
// speedup vs baseline: 4.3138x; 1.4735x over previous
#include <cuda_runtime.h>
#include <cuda_fp16.h>
#include <cstdint>
#include <cstddef>

#define NB 4
#define HH 256
#define WW 256
#define CC 96
#define NF 4
#define CT 32                   // channels per CTA
#define NJ 16                   // chunks per row
#define CL 16                   // chunk length
#define NTHR 512                // NJ * CT

// hscan input tile xs (floats): [j: JSX][i: ISX][c]
#define ISX 34
#define JSX 546                 // 16*34+2 ; bytes 2184 (8B-aligned), word%32==2
// ys / Ysum staging (floats): [j: JSY][i: ISY][c]  (scalar access only)
#define ISY 33
#define JSY 530                 // 16*33+2 ; word%32==2
// vscan rt (halves): [f: FPL][j: JSR][i: ISR][c]
#define ISR 36                  // bytes 72 (8B-aligned)
#define JSR 580                 // 16*36+4 ; bytes 1160
#define FPL 9284                // 16*580+4

__constant__ float c_a[NF]   = {0.1f, 0.3f, 0.4f, 0.8f};
__constant__ float c_cf[NF]  = {0.81818181818f, 0.53846153846f, 0.42857142857f, 0.11111111111f}; // (1-a)/(1+a)
__constant__ float c_i1m[NF] = {1.11111111111f, 1.42857142857f, 1.66666666667f, 5.0f};           // 1/(1-a)

#define PLANE ((size_t)NB * HH * WW * CC)
__device__ __half g_mid[(size_t)NF * PLANE];

__device__ __forceinline__ unsigned h2_bits(__half2 h) {
    return *reinterpret_cast<unsigned*>(&h);
}

__device__ __forceinline__ float powi16(float A, int e) {
    float r = 1.0f, p = A;
    if (e & 1) r *= p;  p *= p;
    if (e & 2) r *= p;  p *= p;
    if (e & 4) r *= p;  p *= p;
    if (e & 8) r *= p;
    return r;
}

// ---------------------------------------------------------------------------
// Bidirectional chunked scan: Yv[i] = F[i] + G[i] - x[i].  xv is NOT modified.
// j = chunk index (0..15) in low lane bits.
// ---------------------------------------------------------------------------
__device__ __forceinline__ void scan_core(
    const float* __restrict__ xv, float* __restrict__ Yv,
    int j, float a, float A16, float i1m)
{
    const unsigned FM = 0xffffffffu;

    float L = 0.0f, LB = 0.0f;
    #pragma unroll
    for (int i = 0; i < CL; ++i) {
        L  = fmaf(a, L,  xv[i]);
        LB = fmaf(a, LB, xv[CL - 1 - i]);
    }

    float s1 = L, s2 = LB, Ad = A16;
    #pragma unroll
    for (int d = 1; d < 16; d <<= 1) {
        float u1 = __shfl_up_sync(FM, s1, d, 16);
        float u2 = __shfl_down_sync(FM, s2, d, 16);
        if (j >= d)     s1 = fmaf(Ad, u1, s1);
        if (j + d < 16) s2 = fmaf(Ad, u2, s2);
        Ad *= Ad;
    }
    float P  = __shfl_up_sync(FM, s1, 1, 16);
    float Pb = __shfl_down_sync(FM, s2, 1, 16);
    if (j == 15) Pb = 0.0f;

    float x0 = __shfl_sync(FM, xv[0], 0, 16);
    float c0 = x0 * i1m;
    float cin = (j == 0) ? c0 : fmaf(powi16(A16, j), c0, P);

    float Ftail = fmaf(A16, cin, L);
    float F255  = __shfl_sync(FM, Ftail, 15, 16);
    float gin   = fmaf(powi16(A16, 15 - j), F255, Pb);

    float tf = cin, tb = gin;
    #pragma unroll
    for (int k = 0; k < CL; ++k) {
        const int ib = CL - 1 - k;
        tf = fmaf(a, tf, xv[k]);
        tb = fmaf(a, tb, xv[ib]);
        if (k < CL / 2) {
            Yv[k]  = tf;
            Yv[ib] = tb - xv[ib];
        } else {
            Yv[k]  += tf;
            Yv[ib] += tb - xv[ib];
        }
    }
}

// Accumulating variant for vscan: Ysum[i] += wt * (F[i] + G[i] - x[i]).
__device__ __forceinline__ void scan_accum(
    const float* __restrict__ xv, float* __restrict__ Ysum, float wt,
    int j, float a, float A16, float i1m)
{
    const unsigned FM = 0xffffffffu;

    float L = 0.0f, LB = 0.0f;
    #pragma unroll
    for (int i = 0; i < CL; ++i) {
        L  = fmaf(a, L,  xv[i]);
        LB = fmaf(a, LB, xv[CL - 1 - i]);
    }

    float s1 = L, s2 = LB, Ad = A16;
    #pragma unroll
    for (int d = 1; d < 16; d <<= 1) {
        float u1 = __shfl_up_sync(FM, s1, d, 16);
        float u2 = __shfl_down_sync(FM, s2, d, 16);
        if (j >= d)     s1 = fmaf(Ad, u1, s1);
        if (j + d < 16) s2 = fmaf(Ad, u2, s2);
        Ad *= Ad;
    }
    float P  = __shfl_up_sync(FM, s1, 1, 16);
    float Pb = __shfl_down_sync(FM, s2, 1, 16);
    if (j == 15) Pb = 0.0f;

    float x0 = __shfl_sync(FM, xv[0], 0, 16);
    float c0 = x0 * i1m;
    float cin = (j == 0) ? c0 : fmaf(powi16(A16, j), c0, P);

    float Ftail = fmaf(A16, cin, L);
    float F255  = __shfl_sync(FM, Ftail, 15, 16);
    float gin   = fmaf(powi16(A16, 15 - j), F255, Pb);

    float tf = cin, tb = gin;
    #pragma unroll
    for (int k = 0; k < CL; ++k) {
        const int ib = CL - 1 - k;
        tf = fmaf(a, tf, xv[k]);
        tb = fmaf(a, tb, xv[ib]);
        Ysum[k]  = fmaf(wt, tf, Ysum[k]);
        Ysum[ib] = fmaf(wt, tb - xv[ib], Ysum[ib]);
    }
}

// ---------------------------------------------------------------------------
// K1: horizontal pass. CTA = (cblk of 32c, h, n). 512 threads = (j, c).
// Each thread scans all 4 filters over the same xv.
// ---------------------------------------------------------------------------
__global__ void __launch_bounds__(NTHR, 2) hscan_k(const float* __restrict__ x) {
    const int cblk = blockIdx.x, h = blockIdx.y, n = blockIdx.z;
    extern __shared__ float sm1[];
    float* xs = sm1;                  // [NJ][ISX][CT] strides JSX/ISX
    float* ys = sm1 + NJ * JSX;       // [NJ][ISY][CT] strides JSY/ISY (per-f reuse)

    const int tid = threadIdx.x;
    const float* src = x + ((size_t)(n * HH + h) * WW) * CC + cblk * CT;

    // load: 4 rounds; warp covers 4 consecutive w (8 lanes x 16B each)
    #pragma unroll
    for (int r = 0; r < 4; ++r) {
        int u = tid + r * NTHR;
        int w = u >> 3, cl = u & 7;
        float4 v = *(const float4*)(src + (size_t)w * CC + cl * 4);
        float* d = xs + (w >> 4) * JSX + (w & 15) * ISX + cl * 4;
        *(float2*)(d)     = make_float2(v.x, v.y);
        *(float2*)(d + 2) = make_float2(v.z, v.w);
    }
    __syncthreads();

    const int j = tid & 15;
    const int c = tid >> 4;           // 0..31

    float xv[CL];
    {
        const float* xp = xs + j * JSX + c;
        #pragma unroll
        for (int i = 0; i < CL; ++i) xv[i] = xp[i * ISX];
    }

    // pack-loop thread mapping (constant across f)
    const int w2 = tid >> 1;          // 0..255
    const int hr = tid & 1;           // which 16-channel half
    const int pj = w2 >> 4, pi = w2 & 15;

    #pragma unroll
    for (int f = 0; f < NF; ++f) {
        const float a = c_a[f];
        const float A8 = powi16(a, 8);
        const float A16 = A8 * A8;
        const float cf = c_cf[f];

        float Yv[CL];
        scan_core(xv, Yv, j, a, A16, c_i1m[f]);

        float* yp = ys + j * JSY + c;
        #pragma unroll
        for (int i = 0; i < CL; ++i)
            yp[i * ISY] = cf * Yv[i];
        __syncthreads();

        // pack: read 16 consecutive channels (scalar, conflict-free), 32B store
        {
            const float* yq = ys + pj * JSY + pi * ISY + hr * 16;
            float v0 = yq[0],  v1 = yq[1],  v2 = yq[2],  v3 = yq[3];
            float v4 = yq[4],  v5 = yq[5],  v6 = yq[6],  v7 = yq[7];
            float v8 = yq[8],  v9 = yq[9],  vA = yq[10], vB = yq[11];
            float vC = yq[12], vD = yq[13], vE = yq[14], vF = yq[15];
            uint4 o0, o1;
            o0.x = h2_bits(__floats2half2_rn(v0, v1));
            o0.y = h2_bits(__floats2half2_rn(v2, v3));
            o0.z = h2_bits(__floats2half2_rn(v4, v5));
            o0.w = h2_bits(__floats2half2_rn(v6, v7));
            o1.x = h2_bits(__floats2half2_rn(v8, v9));
            o1.y = h2_bits(__floats2half2_rn(vA, vB));
            o1.z = h2_bits(__floats2half2_rn(vC, vD));
            o1.w = h2_bits(__floats2half2_rn(vE, vF));
            __half* pb = g_mid + (size_t)f * PLANE
                       + ((size_t)(n * HH + h) * WW + w2) * CC + cblk * CT + hr * 16;
            *(uint4*)(pb)     = o0;
            *(uint4*)(pb + 8) = o1;
        }
        __syncthreads();   // ys reusable for next f
    }
}

// ---------------------------------------------------------------------------
// K2: vertical pass + softmax + weighted combine. CTA = (cblk of 32c, w, n).
// Each thread scans all 4 filters, accumulating the weighted sum in registers.
// ---------------------------------------------------------------------------
__global__ void __launch_bounds__(NTHR, 2) vscan_k(float* __restrict__ out,
                                                   const float* __restrict__ gl) {
    const int cblk = blockIdx.x, w = blockIdx.y, n = blockIdx.z;
    extern __shared__ float sm2[];
    __half* rt  = (__half*)sm2;                       // [NF][NJ][ISR][CT]
    float*  Ys  = sm2 + (NF * FPL + 2) / 2;           // [NJ][ISY][CT] (FPL*4 halves even)
    float*  wsm = Ys + NJ * JSY;                      // [NF][CT]

    const int tid = threadIdx.x;

    // per-channel softmax * cf (32 threads)
    if (tid < CT) {
        int c = cblk * CT + tid;
        float v0 = gl[0 * CC + c], v1 = gl[1 * CC + c];
        float v2 = gl[2 * CC + c], v3 = gl[3 * CC + c];
        float m = fmaxf(fmaxf(v0, v1), fmaxf(v2, v3));
        float e0 = expf(v0 - m), e1 = expf(v1 - m);
        float e2 = expf(v2 - m), e3 = expf(v3 - m);
        float r = 1.0f / (e0 + e1 + e2 + e3);
        wsm[0 * CT + tid] = e0 * r * c_cf[0];
        wsm[1 * CT + tid] = e1 * r * c_cf[1];
        wsm[2 * CT + tid] = e2 * r * c_cf[2];
        wsm[3 * CT + tid] = e3 * r * c_cf[3];
    }

    // load: 8 rounds; warp covers 8 consecutive (f,h) rows x 4 lanes x 16B
    #pragma unroll
    for (int r = 0; r < 8; ++r) {
        int u = tid + r * NTHR;
        int row = u >> 2, cl = u & 3;
        int f = row >> 8, h = row & 255;
        const __half* p = g_mid + (size_t)f * PLANE
                        + ((size_t)(n * HH + h) * WW + w) * CC + cblk * CT + cl * 8;
        uint4 v = *(const uint4*)p;
        __half* d = rt + f * FPL + (h >> 4) * JSR + (h & 15) * ISR + cl * 8;
        *(uint2*)(d)     = make_uint2(v.x, v.y);
        *(uint2*)(d + 4) = make_uint2(v.z, v.w);
    }
    __syncthreads();

    const int j = tid & 15;
    const int c = tid >> 4;           // 0..31

    float Ysum[CL];
    #pragma unroll
    for (int i = 0; i < CL; ++i) Ysum[i] = 0.0f;

    #pragma unroll
    for (int f = 0; f < NF; ++f) {
        const float a = c_a[f];
        const float A8 = powi16(a, 8);
        const float A16 = A8 * A8;
        const float wt = wsm[f * CT + c];

        float xv[CL];
        const __half* rp = rt + f * FPL + j * JSR + c;
        #pragma unroll
        for (int i = 0; i < CL; ++i) xv[i] = __half2float(rp[i * ISR]);

        scan_accum(xv, Ysum, wt, j, a, A16, c_i1m[f]);
    }

    {
        float* yp = Ys + j * JSY + c;
        #pragma unroll
        for (int i = 0; i < CL; ++i)
            yp[i * ISY] = Ysum[i];
    }
    __syncthreads();

    // output: full-line stores (32c x 4B = 128B per h row)
    #pragma unroll
    for (int t = 0; t < 2; ++t) {
        int u = tid + t * NTHR;
        int hh = u >> 2, cq = u & 3;
        const float* bq = Ys + (hh >> 4) * JSY + (hh & 15) * ISY + cq * 8;
        float s0 = bq[0], s1 = bq[1], s2 = bq[2], s3 = bq[3];
        float s4 = bq[4], s5 = bq[5], s6 = bq[6], s7 = bq[7];
        float* ob = out + ((size_t)(n * HH + hh) * WW + w) * CC + cblk * CT + cq * 8;
        *(float4*)(ob)     = make_float4(s0, s1, s2, s3);
        *(float4*)(ob + 4) = make_float4(s4, s5, s6, s7);
    }
}

// ---------------------------------------------------------------------------
extern "C" void kernel_launch(void* const* d_in, const int* in_sizes, int n_in,
                              void* d_out, int out_size) {
    const float* x  = (const float*)d_in[0];
    const float* gl = (const float*)d_in[1];
    float* out = (float*)d_out;

    const int smem1 = (NJ * JSX + NJ * JSY) * (int)sizeof(float);
    const int smem2 = (NF * FPL + 2) * (int)sizeof(__half)
                    + (NJ * JSY + NF * CT) * (int)sizeof(float);

    cudaFuncSetAttribute(hscan_k, cudaFuncAttributeMaxDynamicSharedMemorySize, smem1);
    cudaFuncSetAttribute(vscan_k, cudaFuncAttributeMaxDynamicSharedMemorySize, smem2);

    dim3 g1(CC / CT, HH, NB);
    hscan_k<<<g1, NTHR, smem1>>>(x);

    dim3 g2(CC / CT, WW, NB);
    vscan_k<<<g2, NTHR, smem2>>>(out, gl);

    (void)in_sizes; (void)n_in; (void)out_size;
}

// round 11
// speedup vs baseline: 4.7072x; 1.0912x over previous
#include <cuda_runtime.h>
#include <cuda_fp16.h>
#include <cstdint>
#include <cstddef>

#define NB 4
#define HH 256
#define WW 256
#define CC 96
#define NF 4
#define CT 32                   // channels per CTA
#define NCB (CC / CT)           // 3 channel blocks
#define NJ 16                   // chunks per row
#define CL 16                   // chunk length
#define NTHR 512                // NJ * CT

// hscan input tile xs (floats): [j: JSX][i: ISX][c]
#define ISX 34
#define JSX 546                 // 16*34+2
// ys / Ys staging (floats): [j: JSY][i: ISY][c]  (scalar access only)
#define ISY 33
#define JSY 530                 // 16*33+2
// vscan rt (halves): [f: FPL][j: JSR][i: ISR][c]
#define ISR 36
#define JSR 580
#define FPL 9284

__constant__ float c_a[NF]   = {0.1f, 0.3f, 0.4f, 0.8f};
__constant__ float c_cf[NF]  = {0.81818181818f, 0.53846153846f, 0.42857142857f, 0.11111111111f}; // (1-a)/(1+a)
__constant__ float c_i1m[NF] = {1.11111111111f, 1.42857142857f, 1.66666666667f, 5.0f};           // 1/(1-a)

// intermediate: [f][n][cblk][w][h][c32]  -> vscan reads are fully contiguous
#define COLSZ ((size_t)HH * CT)                 // 8192 halves per (w) column
__device__ __half g_mid[(size_t)NF * NB * NCB * WW * COLSZ];
__device__ __forceinline__ size_t mid_base(int f, int n, int cblk, int w) {
    return ((((size_t)f * NB + n) * NCB + cblk) * WW + w) * COLSZ;
}

__device__ __forceinline__ unsigned h2_bits(__half2 h) {
    return *reinterpret_cast<unsigned*>(&h);
}

__device__ __forceinline__ float powi16(float A, int e) {
    float r = 1.0f, p = A;
    if (e & 1) r *= p;  p *= p;
    if (e & 2) r *= p;  p *= p;
    if (e & 4) r *= p;  p *= p;
    if (e & 8) r *= p;
    return r;
}

// ---------------------------------------------------------------------------
// Bidirectional chunked scan: Yv[i] = F[i] + G[i] - x[i].  xv is NOT modified.
// ---------------------------------------------------------------------------
__device__ __forceinline__ void scan_core(
    const float* __restrict__ xv, float* __restrict__ Yv,
    int j, float a, float A16, float i1m)
{
    const unsigned FM = 0xffffffffu;

    float L = 0.0f, LB = 0.0f;
    #pragma unroll
    for (int i = 0; i < CL; ++i) {
        L  = fmaf(a, L,  xv[i]);
        LB = fmaf(a, LB, xv[CL - 1 - i]);
    }

    float s1 = L, s2 = LB, Ad = A16;
    #pragma unroll
    for (int d = 1; d < 16; d <<= 1) {
        float u1 = __shfl_up_sync(FM, s1, d, 16);
        float u2 = __shfl_down_sync(FM, s2, d, 16);
        if (j >= d)     s1 = fmaf(Ad, u1, s1);
        if (j + d < 16) s2 = fmaf(Ad, u2, s2);
        Ad *= Ad;
    }
    float P  = __shfl_up_sync(FM, s1, 1, 16);
    float Pb = __shfl_down_sync(FM, s2, 1, 16);
    if (j == 15) Pb = 0.0f;

    float x0 = __shfl_sync(FM, xv[0], 0, 16);
    float c0 = x0 * i1m;
    float cin = (j == 0) ? c0 : fmaf(powi16(A16, j), c0, P);

    float Ftail = fmaf(A16, cin, L);
    float F255  = __shfl_sync(FM, Ftail, 15, 16);
    float gin   = fmaf(powi16(A16, 15 - j), F255, Pb);

    float tf = cin, tb = gin;
    #pragma unroll
    for (int k = 0; k < CL; ++k) {
        const int ib = CL - 1 - k;
        tf = fmaf(a, tf, xv[k]);
        tb = fmaf(a, tb, xv[ib]);
        if (k < CL / 2) {
            Yv[k]  = tf;
            Yv[ib] = tb - xv[ib];
        } else {
            Yv[k]  += tf;
            Yv[ib] += tb - xv[ib];
        }
    }
}

// Accumulating variant: Ysum[i] += wt * (F[i] + G[i] - x[i]).
__device__ __forceinline__ void scan_accum(
    const float* __restrict__ xv, float* __restrict__ Ysum, float wt,
    int j, float a, float A16, float i1m)
{
    const unsigned FM = 0xffffffffu;

    float L = 0.0f, LB = 0.0f;
    #pragma unroll
    for (int i = 0; i < CL; ++i) {
        L  = fmaf(a, L,  xv[i]);
        LB = fmaf(a, LB, xv[CL - 1 - i]);
    }

    float s1 = L, s2 = LB, Ad = A16;
    #pragma unroll
    for (int d = 1; d < 16; d <<= 1) {
        float u1 = __shfl_up_sync(FM, s1, d, 16);
        float u2 = __shfl_down_sync(FM, s2, d, 16);
        if (j >= d)     s1 = fmaf(Ad, u1, s1);
        if (j + d < 16) s2 = fmaf(Ad, u2, s2);
        Ad *= Ad;
    }
    float P  = __shfl_up_sync(FM, s1, 1, 16);
    float Pb = __shfl_down_sync(FM, s2, 1, 16);
    if (j == 15) Pb = 0.0f;

    float x0 = __shfl_sync(FM, xv[0], 0, 16);
    float c0 = x0 * i1m;
    float cin = (j == 0) ? c0 : fmaf(powi16(A16, j), c0, P);

    float Ftail = fmaf(A16, cin, L);
    float F255  = __shfl_sync(FM, Ftail, 15, 16);
    float gin   = fmaf(powi16(A16, 15 - j), F255, Pb);

    float tf = cin, tb = gin;
    #pragma unroll
    for (int k = 0; k < CL; ++k) {
        const int ib = CL - 1 - k;
        tf = fmaf(a, tf, xv[k]);
        tb = fmaf(a, tb, xv[ib]);
        Ysum[k]  = fmaf(wt, tf, Ysum[k]);
        Ysum[ib] = fmaf(wt, tb - xv[ib], Ysum[ib]);
    }
}

// ---------------------------------------------------------------------------
// K1: horizontal pass. CTA = (cblk of 32c, h, n). 512 threads = (j, c).
// Double-buffered ys: 4 barriers total.
// ---------------------------------------------------------------------------
__global__ void __launch_bounds__(NTHR, 2) hscan_k(const float* __restrict__ x) {
    const int cblk = blockIdx.x, h = blockIdx.y, n = blockIdx.z;
    extern __shared__ float sm1[];
    float* xs  = sm1;                     // [NJ][ISX][CT]
    float* ys0 = sm1 + NJ * JSX;          // two ys buffers
    float* ys1 = ys0 + NJ * JSY;

    const int tid = threadIdx.x;
    const float* src = x + ((size_t)(n * HH + h) * WW) * CC + cblk * CT;

    #pragma unroll
    for (int r = 0; r < 4; ++r) {
        int u = tid + r * NTHR;
        int w = u >> 3, cl = u & 7;
        float4 v = *(const float4*)(src + (size_t)w * CC + cl * 4);
        float* d = xs + (w >> 4) * JSX + (w & 15) * ISX + cl * 4;
        *(float2*)(d)     = make_float2(v.x, v.y);
        *(float2*)(d + 2) = make_float2(v.z, v.w);
    }
    __syncthreads();

    const int j = tid & 15;
    const int c = tid >> 4;           // 0..31

    float xv[CL];
    {
        const float* xp = xs + j * JSX + c;
        #pragma unroll
        for (int i = 0; i < CL; ++i) xv[i] = xp[i * ISX];
    }

    // pack-loop mapping (constant across f)
    const int w2 = tid >> 1;          // 0..255
    const int hr = tid & 1;           // 16-channel half

    #pragma unroll
    for (int f = 0; f < NF; ++f) {
        const float a = c_a[f];
        const float A8 = powi16(a, 8);
        const float A16 = A8 * A8;
        const float cf = c_cf[f];

        float Yv[CL];
        scan_core(xv, Yv, j, a, A16, c_i1m[f]);

        float* ysb = (f & 1) ? ys1 : ys0;
        float* yp = ysb + j * JSY + c;
        #pragma unroll
        for (int i = 0; i < CL; ++i)
            yp[i * ISY] = cf * Yv[i];
        __syncthreads();

        // pack: 16 consecutive channels (scalar, conflict-free) -> 32B store
        {
            const float* yq = ysb + (w2 >> 4) * JSY + (w2 & 15) * ISY + hr * 16;
            float v0 = yq[0],  v1 = yq[1],  v2 = yq[2],  v3 = yq[3];
            float v4 = yq[4],  v5 = yq[5],  v6 = yq[6],  v7 = yq[7];
            float v8 = yq[8],  v9 = yq[9],  vA = yq[10], vB = yq[11];
            float vC = yq[12], vD = yq[13], vE = yq[14], vF = yq[15];
            uint4 o0, o1;
            o0.x = h2_bits(__floats2half2_rn(v0, v1));
            o0.y = h2_bits(__floats2half2_rn(v2, v3));
            o0.z = h2_bits(__floats2half2_rn(v4, v5));
            o0.w = h2_bits(__floats2half2_rn(v6, v7));
            o1.x = h2_bits(__floats2half2_rn(v8, v9));
            o1.y = h2_bits(__floats2half2_rn(vA, vB));
            o1.z = h2_bits(__floats2half2_rn(vC, vD));
            o1.w = h2_bits(__floats2half2_rn(vE, vF));
            // transposed layout: [f][n][cblk][w2][h][c]
            __half* pb = g_mid + mid_base(f, n, cblk, w2) + (size_t)h * CT + hr * 16;
            *(uint4*)(pb)     = o0;
            *(uint4*)(pb + 8) = o1;
        }
        // no trailing sync: next f writes the other ys buffer
    }
}

// ---------------------------------------------------------------------------
// K2: vertical pass + softmax + weighted combine. CTA = (cblk, w, n).
// Input reads are fully contiguous (16KB per filter).
// ---------------------------------------------------------------------------
__global__ void __launch_bounds__(NTHR, 2) vscan_k(float* __restrict__ out,
                                                   const float* __restrict__ gl) {
    const int cblk = blockIdx.x, w = blockIdx.y, n = blockIdx.z;
    extern __shared__ float sm2[];
    __half* rt  = (__half*)sm2;                       // [NF][NJ][ISR][CT]
    float*  Ys  = sm2 + (NF * FPL + 2) / 2;           // [NJ][ISY][CT]
    float*  wsm = Ys + NJ * JSY;                      // [NF][CT]

    const int tid = threadIdx.x;

    // per-channel softmax * cf (32 threads)
    if (tid < CT) {
        int c = cblk * CT + tid;
        float v0 = gl[0 * CC + c], v1 = gl[1 * CC + c];
        float v2 = gl[2 * CC + c], v3 = gl[3 * CC + c];
        float m = fmaxf(fmaxf(v0, v1), fmaxf(v2, v3));
        float e0 = expf(v0 - m), e1 = expf(v1 - m);
        float e2 = expf(v2 - m), e3 = expf(v3 - m);
        float r = 1.0f / (e0 + e1 + e2 + e3);
        wsm[0 * CT + tid] = e0 * r * c_cf[0];
        wsm[1 * CT + tid] = e1 * r * c_cf[1];
        wsm[2 * CT + tid] = e2 * r * c_cf[2];
        wsm[3 * CT + tid] = e3 * r * c_cf[3];
    }

    // load: fully coalesced; warp reads 512B contiguous per instr
    #pragma unroll
    for (int r = 0; r < 8; ++r) {
        int u = tid + r * NTHR;              // 4096 16B-chunks total
        int f = u >> 10;                     // 1024 chunks per filter
        int rem = u & 1023;
        int h = rem >> 2, cl = rem & 3;
        const __half* p = g_mid + mid_base(f, n, cblk, w) + (size_t)h * CT + cl * 8;
        uint4 v = *(const uint4*)p;
        __half* d = rt + f * FPL + (h >> 4) * JSR + (h & 15) * ISR + cl * 8;
        *(uint2*)(d)     = make_uint2(v.x, v.y);
        *(uint2*)(d + 4) = make_uint2(v.z, v.w);
    }
    __syncthreads();

    const int j = tid & 15;
    const int c = tid >> 4;           // 0..31

    float Ysum[CL];
    #pragma unroll
    for (int i = 0; i < CL; ++i) Ysum[i] = 0.0f;

    #pragma unroll
    for (int f = 0; f < NF; ++f) {
        const float a = c_a[f];
        const float A8 = powi16(a, 8);
        const float A16 = A8 * A8;
        const float wt = wsm[f * CT + c];

        float xv[CL];
        const __half* rp = rt + f * FPL + j * JSR + c;
        #pragma unroll
        for (int i = 0; i < CL; ++i) xv[i] = __half2float(rp[i * ISR]);

        scan_accum(xv, Ysum, wt, j, a, A16, c_i1m[f]);
    }

    {
        float* yp = Ys + j * JSY + c;
        #pragma unroll
        for (int i = 0; i < CL; ++i)
            yp[i * ISY] = Ysum[i];
    }
    __syncthreads();

    // output: full-line stores (32c x 4B = 128B per h row)
    #pragma unroll
    for (int t = 0; t < 2; ++t) {
        int u = tid + t * NTHR;
        int hh = u >> 2, cq = u & 3;
        const float* bq = Ys + (hh >> 4) * JSY + (hh & 15) * ISY + cq * 8;
        float s0 = bq[0], s1 = bq[1], s2 = bq[2], s3 = bq[3];
        float s4 = bq[4], s5 = bq[5], s6 = bq[6], s7 = bq[7];
        float* ob = out + ((size_t)(n * HH + hh) * WW + w) * CC + cblk * CT + cq * 8;
        *(float4*)(ob)     = make_float4(s0, s1, s2, s3);
        *(float4*)(ob + 4) = make_float4(s4, s5, s6, s7);
    }
}

// ---------------------------------------------------------------------------
extern "C" void kernel_launch(void* const* d_in, const int* in_sizes, int n_in,
                              void* d_out, int out_size) {
    const float* x  = (const float*)d_in[0];
    const float* gl = (const float*)d_in[1];
    float* out = (float*)d_out;

    const int smem1 = (NJ * JSX + 2 * NJ * JSY) * (int)sizeof(float);
    const int smem2 = (NF * FPL + 2) * (int)sizeof(__half)
                    + (NJ * JSY + NF * CT) * (int)sizeof(float);

    cudaFuncSetAttribute(hscan_k, cudaFuncAttributeMaxDynamicSharedMemorySize, smem1);
    cudaFuncSetAttribute(vscan_k, cudaFuncAttributeMaxDynamicSharedMemorySize, smem2);

    dim3 g1(NCB, HH, NB);
    hscan_k<<<g1, NTHR, smem1>>>(x);

    dim3 g2(NCB, WW, NB);
    vscan_k<<<g2, NTHR, smem2>>>(out, gl);

    (void)in_sizes; (void)n_in; (void)out_size;
}

// round 12
// speedup vs baseline: 4.7843x; 1.0164x over previous
#include <cuda_runtime.h>
#include <cuda_fp16.h>
#include <cstdint>
#include <cstddef>

#define NB 4
#define HH 256
#define WW 256
#define CC 96
#define NF 4
#define CT 32                   // channels per CTA
#define NCB (CC / CT)           // 3 channel blocks
#define NJ 16                   // chunks per row/column
#define CL 16                   // chunk length
#define NTHR 512                // NJ * CT

// hscan input tile xs (floats): [j: JSX][i: ISX][c]
#define ISX 34
#define JSX 546                 // 16*34+2
// hscan ys staging (floats): [j: JSY][i: ISY][c]  (scalar access only)
#define ISY 33
#define JSY 530                 // 16*33+2

__constant__ float c_a[NF]   = {0.1f, 0.3f, 0.4f, 0.8f};
__constant__ float c_cf[NF]  = {0.81818181818f, 0.53846153846f, 0.42857142857f, 0.11111111111f}; // (1-a)/(1+a)
__constant__ float c_i1m[NF] = {1.11111111111f, 1.42857142857f, 1.66666666667f, 5.0f};           // 1/(1-a)

// intermediate: [f][n][cblk][w][h][c32]
#define COLSZ ((size_t)HH * CT)                 // 8192 halves per (w) column
__device__ __half g_mid[(size_t)NF * NB * NCB * WW * COLSZ];
__device__ __forceinline__ size_t mid_base(int f, int n, int cblk, int w) {
    return ((((size_t)f * NB + n) * NCB + cblk) * WW + w) * COLSZ;
}

__device__ __forceinline__ unsigned h2_bits(__half2 h) {
    return *reinterpret_cast<unsigned*>(&h);
}

__device__ __forceinline__ float powi16(float A, int e) {
    float r = 1.0f, p = A;
    if (e & 1) r *= p;  p *= p;
    if (e & 2) r *= p;  p *= p;
    if (e & 4) r *= p;  p *= p;
    if (e & 8) r *= p;
    return r;
}

// ---------------------------------------------------------------------------
// Shfl-based bidirectional chunked scan (hscan; j in low lane bits):
// Yv[i] = F[i] + G[i] - x[i].  xv is NOT modified.
// ---------------------------------------------------------------------------
__device__ __forceinline__ void scan_core(
    const float* __restrict__ xv, float* __restrict__ Yv,
    int j, float a, float A16, float i1m)
{
    const unsigned FM = 0xffffffffu;

    float L = 0.0f, LB = 0.0f;
    #pragma unroll
    for (int i = 0; i < CL; ++i) {
        L  = fmaf(a, L,  xv[i]);
        LB = fmaf(a, LB, xv[CL - 1 - i]);
    }

    float s1 = L, s2 = LB, Ad = A16;
    #pragma unroll
    for (int d = 1; d < 16; d <<= 1) {
        float u1 = __shfl_up_sync(FM, s1, d, 16);
        float u2 = __shfl_down_sync(FM, s2, d, 16);
        if (j >= d)     s1 = fmaf(Ad, u1, s1);
        if (j + d < 16) s2 = fmaf(Ad, u2, s2);
        Ad *= Ad;
    }
    float P  = __shfl_up_sync(FM, s1, 1, 16);
    float Pb = __shfl_down_sync(FM, s2, 1, 16);
    if (j == 15) Pb = 0.0f;

    float x0 = __shfl_sync(FM, xv[0], 0, 16);
    float c0 = x0 * i1m;
    float cin = (j == 0) ? c0 : fmaf(powi16(A16, j), c0, P);

    float Ftail = fmaf(A16, cin, L);
    float F255  = __shfl_sync(FM, Ftail, 15, 16);
    float gin   = fmaf(powi16(A16, 15 - j), F255, Pb);

    float tf = cin, tb = gin;
    #pragma unroll
    for (int k = 0; k < CL; ++k) {
        const int ib = CL - 1 - k;
        tf = fmaf(a, tf, xv[k]);
        tb = fmaf(a, tb, xv[ib]);
        if (k < CL / 2) {
            Yv[k]  = tf;
            Yv[ib] = tb - xv[ib];
        } else {
            Yv[k]  += tf;
            Yv[ib] += tb - xv[ib];
        }
    }
}

// ---------------------------------------------------------------------------
// K1: horizontal pass (unchanged from R11). CTA = (cblk, h, n). 512 thr (j,c).
// ---------------------------------------------------------------------------
__global__ void __launch_bounds__(NTHR, 2) hscan_k(const float* __restrict__ x) {
    const int cblk = blockIdx.x, h = blockIdx.y, n = blockIdx.z;
    extern __shared__ float sm1[];
    float* xs  = sm1;                     // [NJ][ISX][CT]
    float* ys0 = sm1 + NJ * JSX;
    float* ys1 = ys0 + NJ * JSY;

    const int tid = threadIdx.x;
    const float* src = x + ((size_t)(n * HH + h) * WW) * CC + cblk * CT;

    #pragma unroll
    for (int r = 0; r < 4; ++r) {
        int u = tid + r * NTHR;
        int w = u >> 3, cl = u & 7;
        float4 v = *(const float4*)(src + (size_t)w * CC + cl * 4);
        float* d = xs + (w >> 4) * JSX + (w & 15) * ISX + cl * 4;
        *(float2*)(d)     = make_float2(v.x, v.y);
        *(float2*)(d + 2) = make_float2(v.z, v.w);
    }
    __syncthreads();

    const int j = tid & 15;
    const int c = tid >> 4;

    float xv[CL];
    {
        const float* xp = xs + j * JSX + c;
        #pragma unroll
        for (int i = 0; i < CL; ++i) xv[i] = xp[i * ISX];
    }

    const int w2 = tid >> 1;
    const int hr = tid & 1;

    #pragma unroll
    for (int f = 0; f < NF; ++f) {
        const float a = c_a[f];
        const float A8 = powi16(a, 8);
        const float A16 = A8 * A8;
        const float cf = c_cf[f];

        float Yv[CL];
        scan_core(xv, Yv, j, a, A16, c_i1m[f]);

        float* ysb = (f & 1) ? ys1 : ys0;
        float* yp = ysb + j * JSY + c;
        #pragma unroll
        for (int i = 0; i < CL; ++i)
            yp[i * ISY] = cf * Yv[i];
        __syncthreads();

        {
            const float* yq = ysb + (w2 >> 4) * JSY + (w2 & 15) * ISY + hr * 16;
            float v0 = yq[0],  v1 = yq[1],  v2 = yq[2],  v3 = yq[3];
            float v4 = yq[4],  v5 = yq[5],  v6 = yq[6],  v7 = yq[7];
            float v8 = yq[8],  v9 = yq[9],  vA = yq[10], vB = yq[11];
            float vC = yq[12], vD = yq[13], vE = yq[14], vF = yq[15];
            uint4 o0, o1;
            o0.x = h2_bits(__floats2half2_rn(v0, v1));
            o0.y = h2_bits(__floats2half2_rn(v2, v3));
            o0.z = h2_bits(__floats2half2_rn(v4, v5));
            o0.w = h2_bits(__floats2half2_rn(v6, v7));
            o1.x = h2_bits(__floats2half2_rn(v8, v9));
            o1.y = h2_bits(__floats2half2_rn(vA, vB));
            o1.z = h2_bits(__floats2half2_rn(vC, vD));
            o1.w = h2_bits(__floats2half2_rn(vE, vF));
            __half* pb = g_mid + mid_base(f, n, cblk, w2) + (size_t)h * CT + hr * 16;
            *(uint4*)(pb)     = o0;
            *(uint4*)(pb + 8) = o1;
        }
    }
}

// ---------------------------------------------------------------------------
// K2: vertical pass, channels-in-lanes. CTA = (cblk, w, n).
// 512 threads: c = tid&31 (lane), j = tid>>5 (warp-uniform chunk index).
// Data path is register/global only; smem carries only chunk tails + weights.
// ---------------------------------------------------------------------------
__global__ void __launch_bounds__(NTHR, 2) vscan_k(float* __restrict__ out,
                                                   const float* __restrict__ gl) {
    const int cblk = blockIdx.x, w = blockIdx.y, n = blockIdx.z;

    __shared__ float Ls [NF][NJ][CT];   // forward chunk tails
    __shared__ float LBs[NF][NJ][CT];   // backward chunk heads
    __shared__ float X0s[NF][CT];       // first element of column (h=0)
    __shared__ float wsm[NF][CT];       // softmax * cf

    const int tid = threadIdx.x;
    const int c = tid & 31;
    const int j = tid >> 5;             // warp-uniform

    // per-channel softmax * cf (warp 0)
    if (tid < CT) {
        int cg = cblk * CT + tid;
        float v0 = gl[0 * CC + cg], v1 = gl[1 * CC + cg];
        float v2 = gl[2 * CC + cg], v3 = gl[3 * CC + cg];
        float m = fmaxf(fmaxf(v0, v1), fmaxf(v2, v3));
        float e0 = expf(v0 - m), e1 = expf(v1 - m);
        float e2 = expf(v2 - m), e3 = expf(v3 - m);
        float r = 1.0f / (e0 + e1 + e2 + e3);
        wsm[0][tid] = e0 * r * c_cf[0];
        wsm[1][tid] = e1 * r * c_cf[1];
        wsm[2][tid] = e2 * r * c_cf[2];
        wsm[3][tid] = e3 * r * c_cf[3];
    }

    float Ysum[CL];
    #pragma unroll
    for (int i = 0; i < CL; ++i) Ysum[i] = 0.0f;

    #pragma unroll
    for (int f = 0; f < NF; ++f) {
        const float a = c_a[f];
        const float A8 = powi16(a, 8);
        const float A16 = A8 * A8;

        // ---- load 16 values: warp-contiguous 64B rows, fully coalesced ----
        float xv[CL];
        {
            const __half* mp = g_mid + mid_base(f, n, cblk, w)
                             + (size_t)(j * CL) * CT + c;
            #pragma unroll
            for (int i = 0; i < CL; ++i)
                xv[i] = __half2float(mp[(size_t)i * CT]);
        }

        // ---- local zero-carry scans ----
        float L = 0.0f, LB = 0.0f;
        #pragma unroll
        for (int i = 0; i < CL; ++i) {
            L  = fmaf(a, L,  xv[i]);
            LB = fmaf(a, LB, xv[CL - 1 - i]);
        }
        Ls [f][j][c] = L;
        LBs[f][j][c] = LB;
        if (j == 0) X0s[f][c] = xv[0];
        __syncthreads();

        // ---- carry chains (Horner over smem; capture at warp-uniform m==j) ----
        float c0 = X0s[f][c] * c_i1m[f];
        float p = c0, cin = c0;
        #pragma unroll
        for (int m = 0; m < NJ; ++m) {
            if (m == j) cin = p;                 // uniform branch
            p = fmaf(A16, p, Ls[f][m][c]);
        }
        float F255 = p;                          // full forward tail
        float q = F255, gin = F255;
        #pragma unroll
        for (int m = NJ - 1; m >= 0; --m) {
            if (m == j) gin = q;                 // uniform branch
            q = fmaf(A16, q, LBs[f][m][c]);
        }

        // ---- fused recompute + weighted accumulate ----
        const float wt = wsm[f][c];
        float tf = cin, tb = gin;
        #pragma unroll
        for (int k = 0; k < CL; ++k) {
            const int ib = CL - 1 - k;
            tf = fmaf(a, tf, xv[k]);
            tb = fmaf(a, tb, xv[ib]);
            Ysum[k]  = fmaf(wt, tf, Ysum[k]);
            Ysum[ib] = fmaf(wt, tb - xv[ib], Ysum[ib]);
        }
    }

    // ---- output: full 128B-line stores straight from registers ----
    {
        float* ob = out + ((size_t)(n * HH + j * CL) * WW + w) * CC + cblk * CT + c;
        #pragma unroll
        for (int i = 0; i < CL; ++i)
            ob[(size_t)i * WW * CC] = Ysum[i];
    }
}

// ---------------------------------------------------------------------------
extern "C" void kernel_launch(void* const* d_in, const int* in_sizes, int n_in,
                              void* d_out, int out_size) {
    const float* x  = (const float*)d_in[0];
    const float* gl = (const float*)d_in[1];
    float* out = (float*)d_out;

    const int smem1 = (NJ * JSX + 2 * NJ * JSY) * (int)sizeof(float);
    cudaFuncSetAttribute(hscan_k, cudaFuncAttributeMaxDynamicSharedMemorySize, smem1);

    dim3 g1(NCB, HH, NB);
    hscan_k<<<g1, NTHR, smem1>>>(x);

    dim3 g2(NCB, WW, NB);
    vscan_k<<<g2, NTHR>>>(out, gl);

    (void)in_sizes; (void)n_in; (void)out_size;
}